// round 4
// baseline (speedup 1.0000x reference)
#include <cuda_runtime.h>
#include <math.h>

// ---------------------------------------------------------------------------
// maps[b] = bilin_up(out0,64)+bilin_up(out1,32)+bilin_up(out2,16) -> 256x256
// scores[b] = max( reflect-pad 5x5 gaussian blur of maps[b] )
// d_out = [256 scores][256*256*256 maps] fp32.
//
// Single kernel: 1024 blocks = (batch, quarter-strip of 64 rows), 128 threads
// = column pairs. Incremental register bilinear caches (no per-row division,
// no gathers in steady state), packed f32x2 math, 16-row smem ring for the
// horizontal-blur halo, register ring for the vertical blur. Final per-batch
// max fused via encoded atomicMax + arrival counter (last block decodes).
// ---------------------------------------------------------------------------

typedef unsigned long long ull;

#define W0 0.18762723f
#define W1 0.20606817f
#define W2 0.21260941f

__device__ __forceinline__ ull pk2(float a, float b) {
    ull r; asm("mov.b64 %0, {%1,%2};" : "=l"(r) : "f"(a), "f"(b)); return r;
}
__device__ __forceinline__ float2 up2(ull v) {
    float2 r; asm("mov.b64 {%0,%1}, %2;" : "=f"(r.x), "=f"(r.y) : "l"(v)); return r;
}
__device__ __forceinline__ ull f2add(ull a, ull b) {
    ull r; asm("add.rn.f32x2 %0,%1,%2;" : "=l"(r) : "l"(a), "l"(b)); return r;
}
__device__ __forceinline__ ull f2mul(ull a, ull b) {
    ull r; asm("mul.rn.f32x2 %0,%1,%2;" : "=l"(r) : "l"(a), "l"(b)); return r;
}
__device__ __forceinline__ ull f2fma(ull a, ull b, ull c) {
    ull r; asm("fma.rn.f32x2 %0,%1,%2,%3;" : "=l"(r) : "l"(a), "l"(b), "l"(c)); return r;
}

// ordered-uint float encoding: enc monotone in float order; 0 < enc(any finite)
__device__ __forceinline__ unsigned enc_f(float f) {
    unsigned u = __float_as_uint(f);
    return (u & 0x80000000u) ? ~u : (u | 0x80000000u);
}
__device__ __forceinline__ float dec_f(unsigned u) {
    return (u & 0x80000000u) ? __uint_as_float(u & 0x7fffffffu)
                             : __uint_as_float(~u);
}

__device__ unsigned g_enc[256];   // zero-init; reset by last block each call
__device__ unsigned g_cnt[256];   // zero-init; reset by last block each call

// per-scale incremental bilinear cache (thread handles columns c0, c1)
template<int H>
struct SC {
    int x0a, x1a, x0b, x1b;
    float fxa, fxb;
    int rlo;         // first staged source row
    int y0, rem;     // y bracket state: num = y*(H-1) = 255*y0 + rem
    float xha, xhb;  // x-lerped values at source row y0+1 (scalars)
    ull xlo2, xdf2;  // packed x-lerp at y0, packed (hi - lo)
};

template<int H>
__device__ __forceinline__ void col_init(SC<H>& c, int c0, int c1, int rlo) {
    int n0 = c0 * (H - 1);
    c.x0a = n0 / 255;
    c.fxa = (float)(n0 - 255 * c.x0a) * (1.0f / 255.0f);
    c.x1a = min(c.x0a + 1, H - 1);
    int n1 = c1 * (H - 1);
    c.x0b = n1 / 255;
    c.fxb = (float)(n1 - 255 * c.x0b) * (1.0f / 255.0f);
    c.x1b = min(c.x0b + 1, H - 1);
    c.rlo = rlo;
}

template<int H>
__device__ __forceinline__ float xl_a(const SC<H>& c, const float* row) {
    float a = row[c.x0a], b = row[c.x1a];
    return fmaf(c.fxa, b - a, a);
}
template<int H>
__device__ __forceinline__ float xl_b(const SC<H>& c, const float* row) {
    float a = row[c.x0b], b = row[c.x1b];
    return fmaf(c.fxb, b - a, a);
}

template<int H>
__device__ __forceinline__ void sc_init(SC<H>& c, const float* sm, int y) {
    int num = y * (H - 1);
    c.y0  = num / 255;
    c.rem = num - 255 * c.y0;
    const float* rlo = sm + (c.y0 - c.rlo) * H;
    const float* rhi = sm + (min(c.y0 + 1, H - 1) - c.rlo) * H;
    float la = xl_a(c, rlo), lb = xl_b(c, rlo);
    c.xha = xl_a(c, rhi);
    c.xhb = xl_b(c, rhi);
    c.xlo2 = pk2(la, lb);
    c.xdf2 = pk2(c.xha - la, c.xhb - lb);
}

template<int H>
__device__ __forceinline__ ull sc_m(const SC<H>& c) {
    float fy = (float)c.rem * (1.0f / 255.0f);
    return f2fma(pk2(fy, fy), c.xdf2, c.xlo2);
}

template<int H>
__device__ __forceinline__ void sc_adv(SC<H>& c, const float* sm) {
    c.rem += (H - 1);
    if (c.rem >= 255) {          // uniform branch (depends only on row)
        c.rem -= 255;
        c.y0++;
        c.xlo2 = f2add(c.xlo2, c.xdf2);       // new lo = old hi
        const float* rhi = sm + (min(c.y0 + 1, H - 1) - c.rlo) * H;
        float nha = xl_a(c, rhi), nhb = xl_b(c, rhi);
        c.xdf2 = pk2(nha - c.xha, nhb - c.xhb);
        c.xha = nha; c.xhb = nhb;
    }
}

#define RING 16

__device__ __forceinline__ void store_mrow(float (*mbuf)[264], int r, float2 mv, int tid) {
    *(float2*)&mbuf[r][2 + 2 * tid] = mv;
    if (tid == 1)        mbuf[r][0]   = mv.x;   // col -2 = reflect col 2
    else if (tid == 0)   mbuf[r][1]   = mv.y;   // col -1 = reflect col 1
    else if (tid == 127) mbuf[r][258] = mv.x;   // col 256 = reflect col 254
    else if (tid == 126) mbuf[r][259] = mv.y;   // col 257 = reflect col 253
}

__device__ __forceinline__ ull hblur_row(const float* mrow, int tid, ull w0p, ull w1p, ull w2p) {
    float2 v01 = *(const float2*)&mrow[2 * tid];
    float2 v23 = *(const float2*)&mrow[2 * tid + 2];
    float2 v45 = *(const float2*)&mrow[2 * tid + 4];
    ull p0 = pk2(v01.x, v01.y);
    ull p1 = pk2(v01.y, v23.x);
    ull p2 = pk2(v23.x, v23.y);
    ull p3 = pk2(v23.y, v45.x);
    ull p4 = pk2(v45.x, v45.y);
    return f2fma(w0p, f2add(p0, p4), f2fma(w1p, f2add(p1, p3), f2mul(w2p, p2)));
}

__global__ void __launch_bounds__(128)
fused_quarter(const float* __restrict__ in0,
              const float* __restrict__ in1,
              const float* __restrict__ in2,
              float* __restrict__ maps,
              float* __restrict__ scores) {
    __shared__ __align__(16) float s0[20 * 64];
    __shared__ __align__(16) float s1[12 * 32];
    __shared__ __align__(16) float s2[8 * 16];
    __shared__ __align__(16) float mbuf[RING][264];
    __shared__ float wred[4];

    const int tid = threadIdx.x;
    const int bx  = blockIdx.x;
    const int b   = bx >> 2;
    const int q   = bx & 3;
    const int yq0 = q * 64;

    // actual source-row window needed by this strip (incl. blur halo)
    const int amin = max(0, yq0 - 2);
    const int amax = min(255, yq0 + 65);
    const int rlo0 = (amin * 63) / 255, rhi0 = min((amax * 63) / 255 + 1, 63);
    const int rlo1 = (amin * 31) / 255, rhi1 = min((amax * 31) / 255 + 1, 31);
    const int rlo2 = (amin * 15) / 255, rhi2 = min((amax * 15) / 255 + 1, 15);

    // stage sources (coalesced float4)
    {
        const float4* g = (const float4*)(in0 + (size_t)b * 4096 + rlo0 * 64);
        int n = (rhi0 - rlo0 + 1) * 16;
        for (int i = tid; i < n; i += 128) ((float4*)s0)[i] = g[i];
    }
    {
        const float4* g = (const float4*)(in1 + (size_t)b * 1024 + rlo1 * 32);
        int n = (rhi1 - rlo1 + 1) * 8;
        for (int i = tid; i < n; i += 128) ((float4*)s1)[i] = g[i];
    }
    {
        const float4* g = (const float4*)(in2 + (size_t)b * 256 + rlo2 * 16);
        int n = (rhi2 - rlo2 + 1) * 4;
        for (int i = tid; i < n; i += 128) ((float4*)s2)[i] = g[i];
    }

    SC<64> cA; SC<32> cB; SC<16> cC;
    col_init(cA, 2 * tid, 2 * tid + 1, rlo0);
    col_init(cB, 2 * tid, 2 * tid + 1, rlo1);
    col_init(cC, 2 * tid, 2 * tid + 1, rlo2);

    const ull w0p = pk2(W0, W0), w1p = pk2(W1, W1), w2p = pk2(W2, W2);

    __syncthreads();

    // ---- prime: h(yq0-2), h(yq0-1)  (reflect at top edge) ----
    {
        int p0 = (q == 0) ? 2 : yq0 - 2;
        int p1 = (q == 0) ? 1 : yq0 - 1;
        sc_init(cA, s0, p0); sc_init(cB, s1, p0); sc_init(cC, s2, p0);
        store_mrow(mbuf, 0, up2(f2add(f2add(sc_m(cA), sc_m(cB)), sc_m(cC))), tid);
        sc_init(cA, s0, p1); sc_init(cB, s1, p1); sc_init(cC, s2, p1);
        store_mrow(mbuf, 1, up2(f2add(f2add(sc_m(cA), sc_m(cB)), sc_m(cC))), tid);
    }
    __syncthreads();
    ull ha = 0, hb = 0;
    ull hc = hblur_row(&mbuf[0][0], tid, w0p, w1p, w2p);   // h(yq0-2)
    ull hd = hblur_row(&mbuf[1][0], tid, w0p, w1p, w2p);   // h(yq0-1)
    __syncthreads();

    // ---- main strip (16-row double-phase ring) ----
    sc_init(cA, s0, yq0); sc_init(cB, s1, yq0); sc_init(cC, s2, yq0);

    float* mout = maps + (size_t)b * 65536;
    float lmax = -INFINITY;
    const int nrows = (q < 3) ? 66 : 64;   // q<3 needs 2 extra h rows below
    int done = 0;

    while (done < nrows) {
        int cnt = min(RING, nrows - done);
        // phase A: compute m rows, store maps + smem ring
        #pragma unroll
        for (int r = 0; r < RING; ++r) {
            if (r < cnt) {
                int y = yq0 + done + r;
                float2 mv = up2(f2add(f2add(sc_m(cA), sc_m(cB)), sc_m(cC)));
                store_mrow(mbuf, r, mv, tid);
                if (y < yq0 + 64)
                    *(float2*)&mout[y * 256 + 2 * tid] = mv;
                sc_adv(cA, s0); sc_adv(cB, s1); sc_adv(cC, s2);
            }
        }
        __syncthreads();
        // phase B: h-blur + register-ring v-blur + max
        #pragma unroll
        for (int r = 0; r < RING; ++r) {
            if (r < cnt) {
                int y = yq0 + done + r;
                ull he = hblur_row(&mbuf[r][0], tid, w0p, w1p, w2p);
                if (y >= yq0 + 2) {
                    ull vv = f2fma(w0p, f2add(ha, he),
                             f2fma(w1p, f2add(hb, hd), f2mul(w2p, hc)));
                    float2 vf = up2(vv);
                    lmax = fmaxf(lmax, fmaxf(vf.x, vf.y));
                }
                ha = hb; hb = hc; hc = hd; hd = he;
            }
        }
        __syncthreads();
        done += cnt;
    }

    if (q == 3) {
        // ring: ha=h252 hb=h253 hc=h254 hd=h255; reflect rows 256->254, 257->253
        ull v254 = f2fma(w0p, f2add(ha, hc), f2fma(w1p, f2add(hb, hd), f2mul(w2p, hc)));
        ull v255 = f2fma(w0p, f2add(hb, hb), f2fma(w1p, f2add(hc, hc), f2mul(w2p, hd)));
        float2 a4 = up2(v254), a5 = up2(v255);
        lmax = fmaxf(lmax, fmaxf(fmaxf(a4.x, a4.y), fmaxf(a5.x, a5.y)));
    }

    // block max -> fused per-batch reduction (deterministic: max is
    // order-independent; last-arriving block decodes and resets scratch)
    #pragma unroll
    for (int off = 16; off; off >>= 1)
        lmax = fmaxf(lmax, __shfl_xor_sync(0xFFFFFFFFu, lmax, off));
    if ((tid & 31) == 0) wred[tid >> 5] = lmax;
    __syncthreads();
    if (tid == 0) {
        float m = fmaxf(fmaxf(wred[0], wred[1]), fmaxf(wred[2], wred[3]));
        atomicMax(&g_enc[b], enc_f(m));
        __threadfence();
        unsigned t = atomicAdd(&g_cnt[b], 1u);
        if (t == 3u) {
            unsigned e = atomicExch(&g_enc[b], 0u);   // read + reset for replay
            scores[b] = dec_f(e);
            atomicExch(&g_cnt[b], 0u);                // reset for replay
        }
    }
}

extern "C" void kernel_launch(void* const* d_in, const int* in_sizes, int n_in,
                              void* d_out, int out_size) {
    const float* out0 = (const float*)d_in[0];  // [256,64,64]
    const float* out1 = (const float*)d_in[1];  // [256,32,32]
    const float* out2 = (const float*)d_in[2];  // [256,16,16]
    float* out = (float*)d_out;

    fused_quarter<<<1024, 128>>>(out0, out1, out2, out + 256, out);
}

// round 5
// speedup vs baseline: 1.3554x; 1.3554x over previous
#include <cuda_runtime.h>
#include <math.h>

// ---------------------------------------------------------------------------
// maps[b] = bilin_up(out0,64)+bilin_up(out1,32)+bilin_up(out2,16) -> 256x256
// scores[b] = max( reflect-pad 5x5 gaussian blur of maps[b] )
// d_out = [256 scores][256*256*256 maps] fp32.
//
// Single kernel: 1024 blocks = (batch, quarter-strip of 64 rows), 128 threads
// = column pairs. Incremental register bilinear caches with incremental fy
// (no per-row I2F/IMUL), packed f32x2 m-compute + v-blur, scalar immediate-FFMA
// h-blur. 8 full phases of 8 rows (no runtime guards). Fused per-batch max via
// encoded atomicMax + arrival counter.
// ---------------------------------------------------------------------------

typedef unsigned long long ull;

#define W0 0.18762723f
#define W1 0.20606817f
#define W2 0.21260941f

__device__ __forceinline__ ull pk2(float a, float b) {
    ull r; asm("mov.b64 %0, {%1,%2};" : "=l"(r) : "f"(a), "f"(b)); return r;
}
__device__ __forceinline__ float2 up2(ull v) {
    float2 r; asm("mov.b64 {%0,%1}, %2;" : "=f"(r.x), "=f"(r.y) : "l"(v)); return r;
}
__device__ __forceinline__ ull f2add(ull a, ull b) {
    ull r; asm("add.rn.f32x2 %0,%1,%2;" : "=l"(r) : "l"(a), "l"(b)); return r;
}
__device__ __forceinline__ ull f2mul(ull a, ull b) {
    ull r; asm("mul.rn.f32x2 %0,%1,%2;" : "=l"(r) : "l"(a), "l"(b)); return r;
}
__device__ __forceinline__ ull f2fma(ull a, ull b, ull c) {
    ull r; asm("fma.rn.f32x2 %0,%1,%2,%3;" : "=l"(r) : "l"(a), "l"(b), "l"(c)); return r;
}

__device__ __forceinline__ unsigned enc_f(float f) {
    unsigned u = __float_as_uint(f);
    return (u & 0x80000000u) ? ~u : (u | 0x80000000u);
}
__device__ __forceinline__ float dec_f(unsigned u) {
    return (u & 0x80000000u) ? __uint_as_float(u & 0x7fffffffu)
                             : __uint_as_float(~u);
}

__device__ unsigned g_enc[256];   // zero-init; reset by last block each call
__device__ unsigned g_cnt[256];   // zero-init; reset by last block each call

// per-scale incremental bilinear cache (thread handles columns c0, c1)
template<int H>
struct SC {
    int   x0a, x0b;      // source column brackets (x1 derived on use)
    float fxa, fxb;
    int   rowoff;        // staged offset of source row y0
    int   y0, rem;       // y*(H-1) = 255*y0 + rem
    float fy;            // rem/255 (incremental)
    float xha, xhb;      // x-lerp at row y0+1 (scalars)
    ull   xlo2, xdf2;    // packed x-lerp at y0, packed (hi - lo)
};

template<int H>
__device__ __forceinline__ float xl(const float* row, int x0, float fx) {
    float a = row[x0];
    float b = row[min(x0 + 1, H - 1)];
    return fmaf(fx, b - a, a);
}

template<int H>
__device__ __forceinline__ void col_init(SC<H>& c, int c0) {
    int n0 = c0 * (H - 1);
    c.x0a = n0 / 255;
    c.fxa = (float)(n0 - 255 * c.x0a) * (1.0f / 255.0f);
    int n1 = (c0 + 1) * (H - 1);
    c.x0b = n1 / 255;
    c.fxb = (float)(n1 - 255 * c.x0b) * (1.0f / 255.0f);
}

template<int H>
__device__ __forceinline__ void sc_init(SC<H>& c, const float* sm, int y, int rlo) {
    int num = y * (H - 1);
    c.y0  = num / 255;
    c.rem = num - 255 * c.y0;
    c.fy  = (float)c.rem * (1.0f / 255.0f);
    c.rowoff = (c.y0 - rlo) * H;
    const float* rl = sm + c.rowoff;
    const float* rh = rl + ((c.y0 < H - 1) ? H : 0);
    float la = xl<H>(rl, c.x0a, c.fxa);
    float lb = xl<H>(rl, c.x0b, c.fxb);
    c.xha = xl<H>(rh, c.x0a, c.fxa);
    c.xhb = xl<H>(rh, c.x0b, c.fxb);
    c.xlo2 = pk2(la, lb);
    c.xdf2 = pk2(c.xha - la, c.xhb - lb);
}

template<int H>
__device__ __forceinline__ ull sc_m(const SC<H>& c) {
    return f2fma(pk2(c.fy, c.fy), c.xdf2, c.xlo2);
}

template<int H>
__device__ __forceinline__ void sc_adv(SC<H>& c, const float* sm) {
    c.rem += (H - 1);
    c.fy  += (float)(H - 1) * (1.0f / 255.0f);   // FADD immediate
    if (c.rem >= 255) {                          // uniform, rarely taken
        c.rem -= 255;
        c.fy  -= 1.0f;
        c.y0++;
        c.rowoff += H;
        c.xlo2 = f2add(c.xlo2, c.xdf2);          // new lo = old hi
        const float* rh = sm + c.rowoff + ((c.y0 < H - 1) ? H : 0);
        float nha = xl<H>(rh, c.x0a, c.fxa);
        float nhb = xl<H>(rh, c.x0b, c.fxb);
        c.xdf2 = pk2(nha - c.xha, nhb - c.xhb);
        c.xha = nha; c.xhb = nhb;
    }
}

// scalar h-blur from smem row (immediate-form FFMAs; no packing movs)
__device__ __forceinline__ ull hblur_row(const float* row) {
    float2 v01 = *(const float2*)&row[0];
    float2 v23 = *(const float2*)&row[2];
    float2 v45 = *(const float2*)&row[4];
    float o0 = W0 * v01.x + W1 * v01.y + W2 * v23.x + W1 * v23.y + W0 * v45.x;
    float o1 = W0 * v01.y + W1 * v23.x + W2 * v23.y + W1 * v45.x + W0 * v45.y;
    return pk2(o0, o1);
}

__global__ void __launch_bounds__(128, 7)
fused_quarter(const float* __restrict__ in0,
              const float* __restrict__ in1,
              const float* __restrict__ in2,
              float* __restrict__ maps,
              float* __restrict__ scores) {
    __shared__ __align__(16) float s0[20 * 64];
    __shared__ __align__(16) float s1[12 * 32];
    __shared__ __align__(16) float s2[8 * 16];
    __shared__ __align__(16) float mbuf[8][264];
    __shared__ float wred[4];

    const int tid = threadIdx.x;
    const int bx  = blockIdx.x;
    const int b   = bx >> 2;
    const int q   = bx & 3;
    const int yq0 = q * 64;

    const int amin = max(0, yq0 - 2);
    const int amax = min(255, yq0 + 65);
    const int rlo0 = (amin * 63) / 255;
    const int rlo1 = (amin * 31) / 255;
    const int rlo2 = (amin * 15) / 255;

    // stage sources (coalesced float4)
    {
        const int rhi = min((amax * 63) / 255 + 1, 63);
        const float4* g = (const float4*)(in0 + (size_t)b * 4096 + rlo0 * 64);
        int n = (rhi - rlo0 + 1) * 16;
        for (int i = tid; i < n; i += 128) ((float4*)s0)[i] = g[i];
    }
    {
        const int rhi = min((amax * 31) / 255 + 1, 31);
        const float4* g = (const float4*)(in1 + (size_t)b * 1024 + rlo1 * 32);
        int n = (rhi - rlo1 + 1) * 8;
        for (int i = tid; i < n; i += 128) ((float4*)s1)[i] = g[i];
    }
    {
        const int rhi = min((amax * 15) / 255 + 1, 15);
        const float4* g = (const float4*)(in2 + (size_t)b * 256 + rlo2 * 16);
        int n = (rhi - rlo2 + 1) * 4;
        for (int i = tid; i < n; i += 128) ((float4*)s2)[i] = g[i];
    }

    SC<64> cA; SC<32> cB; SC<16> cC;
    col_init(cA, 2 * tid);
    col_init(cB, 2 * tid);
    col_init(cC, 2 * tid);

    const bool eL0 = (tid == 1), eL1 = (tid == 0);
    const bool eR0 = (tid == 127), eR1 = (tid == 126);
    const ull w0p = pk2(W0, W0), w1p = pk2(W1, W1), w2p = pk2(W2, W2);

    __syncthreads();

    // ---- prime: h(yq0-2), h(yq0-1) (reflect at top edge) ----
    {
        int p0 = (q == 0) ? 2 : yq0 - 2;
        int p1 = (q == 0) ? 1 : yq0 - 1;
        sc_init(cA, s0, p0, rlo0); sc_init(cB, s1, p0, rlo1); sc_init(cC, s2, p0, rlo2);
        float2 mv = up2(f2add(f2add(sc_m(cA), sc_m(cB)), sc_m(cC)));
        *(float2*)&mbuf[0][2 + 2 * tid] = mv;
        if (eL0) mbuf[0][0] = mv.x;
        if (eL1) mbuf[0][1] = mv.y;
        if (eR0) mbuf[0][258] = mv.x;
        if (eR1) mbuf[0][259] = mv.y;
        sc_init(cA, s0, p1, rlo0); sc_init(cB, s1, p1, rlo1); sc_init(cC, s2, p1, rlo2);
        mv = up2(f2add(f2add(sc_m(cA), sc_m(cB)), sc_m(cC)));
        *(float2*)&mbuf[1][2 + 2 * tid] = mv;
        if (eL0) mbuf[1][0] = mv.x;
        if (eL1) mbuf[1][1] = mv.y;
        if (eR0) mbuf[1][258] = mv.x;
        if (eR1) mbuf[1][259] = mv.y;
    }
    __syncthreads();
    ull ha = 0, hb = 0;
    ull hc = hblur_row(&mbuf[0][2 * tid]);
    ull hd = hblur_row(&mbuf[1][2 * tid]);
    __syncthreads();

    // ---- main strip: 8 phases x 8 rows, fixed trip counts ----
    sc_init(cA, s0, yq0, rlo0); sc_init(cB, s1, yq0, rlo1); sc_init(cC, s2, yq0, rlo2);

    float* mp = maps + (size_t)b * 65536 + (size_t)yq0 * 256 + 2 * tid;
    float lmax = -INFINITY;

    for (int p = 0; p < 8; ++p) {
        // phase A: compute 8 m-rows, store maps + smem ring
        #pragma unroll
        for (int r = 0; r < 8; ++r) {
            float2 mv = up2(f2add(f2add(sc_m(cA), sc_m(cB)), sc_m(cC)));
            *(float2*)&mbuf[r][2 + 2 * tid] = mv;
            if (eL0) mbuf[r][0] = mv.x;
            if (eL1) mbuf[r][1] = mv.y;
            if (eR0) mbuf[r][258] = mv.x;
            if (eR1) mbuf[r][259] = mv.y;
            *(float2*)(mp + r * 256) = mv;
            sc_adv(cA, s0); sc_adv(cB, s1); sc_adv(cC, s2);
        }
        mp += 2048;
        __syncthreads();
        // phase B: h-blur + register-ring v-blur + max
        #pragma unroll
        for (int r = 0; r < 8; ++r) {
            ull he = hblur_row(&mbuf[r][2 * tid]);
            ull vv = f2fma(w0p, f2add(ha, he),
                     f2fma(w1p, f2add(hb, hd), f2mul(w2p, hc)));
            float2 vf = up2(vv);
            if (r >= 2 || p != 0)
                lmax = fmaxf(lmax, fmaxf(vf.x, vf.y));
            ha = hb; hb = hc; hc = hd; hd = he;
        }
        __syncthreads();
    }

    if (q < 3) {
        // two extra h rows (yq0+64, yq0+65) finish v rows yq0+62, yq0+63
        #pragma unroll
        for (int e = 0; e < 2; ++e) {
            float2 mv = up2(f2add(f2add(sc_m(cA), sc_m(cB)), sc_m(cC)));
            *(float2*)&mbuf[e][2 + 2 * tid] = mv;
            if (eL0) mbuf[e][0] = mv.x;
            if (eL1) mbuf[e][1] = mv.y;
            if (eR0) mbuf[e][258] = mv.x;
            if (eR1) mbuf[e][259] = mv.y;
            sc_adv(cA, s0); sc_adv(cB, s1); sc_adv(cC, s2);
        }
        __syncthreads();
        #pragma unroll
        for (int e = 0; e < 2; ++e) {
            ull he = hblur_row(&mbuf[e][2 * tid]);
            ull vv = f2fma(w0p, f2add(ha, he),
                     f2fma(w1p, f2add(hb, hd), f2mul(w2p, hc)));
            float2 vf = up2(vv);
            lmax = fmaxf(lmax, fmaxf(vf.x, vf.y));
            ha = hb; hb = hc; hc = hd; hd = he;
        }
    } else {
        // ring holds h252..h255; reflect rows 256->254, 257->253
        ull v254 = f2fma(w0p, f2add(ha, hc), f2fma(w1p, f2add(hb, hd), f2mul(w2p, hc)));
        ull v255 = f2fma(w0p, f2add(hb, hb), f2fma(w1p, f2add(hc, hc), f2mul(w2p, hd)));
        float2 a4 = up2(v254), a5 = up2(v255);
        lmax = fmaxf(lmax, fmaxf(fmaxf(a4.x, a4.y), fmaxf(a5.x, a5.y)));
    }

    // block max -> fused per-batch reduction (max is order-independent;
    // last-arriving block decodes and resets scratch for graph replay)
    #pragma unroll
    for (int off = 16; off; off >>= 1)
        lmax = fmaxf(lmax, __shfl_xor_sync(0xFFFFFFFFu, lmax, off));
    if ((tid & 31) == 0) wred[tid >> 5] = lmax;
    __syncthreads();
    if (tid == 0) {
        float m = fmaxf(fmaxf(wred[0], wred[1]), fmaxf(wred[2], wred[3]));
        atomicMax(&g_enc[b], enc_f(m));
        __threadfence();
        unsigned t = atomicAdd(&g_cnt[b], 1u);
        if (t == 3u) {
            unsigned e = atomicExch(&g_enc[b], 0u);
            scores[b] = dec_f(e);
            atomicExch(&g_cnt[b], 0u);
        }
    }
}

extern "C" void kernel_launch(void* const* d_in, const int* in_sizes, int n_in,
                              void* d_out, int out_size) {
    const float* out0 = (const float*)d_in[0];  // [256,64,64]
    const float* out1 = (const float*)d_in[1];  // [256,32,32]
    const float* out2 = (const float*)d_in[2];  // [256,16,16]
    float* out = (float*)d_out;

    fused_quarter<<<1024, 128>>>(out0, out1, out2, out + 256, out);
}

// round 6
// speedup vs baseline: 1.4389x; 1.0616x over previous
#include <cuda_runtime.h>
#include <math.h>

// ---------------------------------------------------------------------------
// maps[b] = bilin_up(out0,64)+bilin_up(out1,32)+bilin_up(out2,16) -> 256x256
// scores[b] = max( reflect-pad 5x5 gaussian blur of maps[b] )
// d_out = [256 scores][256*256*256 maps] fp32.
//
// 1024 blocks = (batch, 64-row quarter strip), 128 threads = column pairs.
// Incremental bilinear: float-only y-bracket tracking (fy>=1 wrap, exact-int
// init per strip), x-tables in smem (read only on wrap), packed f32x2 math
// end-to-end, 8-row smem ring for the h-blur column halo, register ring for
// the v-blur. Fused per-batch max via encoded atomicMax + arrival counter.
// ---------------------------------------------------------------------------

typedef unsigned long long ull;

#define W0 0.18762723f
#define W1 0.20606817f
#define W2 0.21260941f

__device__ __forceinline__ ull pk2(float a, float b) {
    ull r; asm("mov.b64 %0, {%1,%2};" : "=l"(r) : "f"(a), "f"(b)); return r;
}
__device__ __forceinline__ float2 up2(ull v) {
    float2 r; asm("mov.b64 {%0,%1}, %2;" : "=f"(r.x), "=f"(r.y) : "l"(v)); return r;
}
__device__ __forceinline__ ull f2add(ull a, ull b) {
    ull r; asm("add.rn.f32x2 %0,%1,%2;" : "=l"(r) : "l"(a), "l"(b)); return r;
}
__device__ __forceinline__ ull f2mul(ull a, ull b) {
    ull r; asm("mul.rn.f32x2 %0,%1,%2;" : "=l"(r) : "l"(a), "l"(b)); return r;
}
__device__ __forceinline__ ull f2fma(ull a, ull b, ull c) {
    ull r; asm("fma.rn.f32x2 %0,%1,%2,%3;" : "=l"(r) : "l"(a), "l"(b), "l"(c)); return r;
}

__device__ __forceinline__ unsigned enc_f(float f) {
    unsigned u = __float_as_uint(f);
    return (u & 0x80000000u) ? ~u : (u | 0x80000000u);
}
__device__ __forceinline__ float dec_f(unsigned u) {
    return (u & 0x80000000u) ? __uint_as_float(u & 0x7fffffffu)
                             : __uint_as_float(~u);
}

__device__ unsigned g_enc[256];   // zero-init; reset by last block each call
__device__ unsigned g_cnt[256];   // zero-init; reset by last block each call

// x-lerp for a column pair from an explicit index/frac table entry
__device__ __forceinline__ float2 xl2(const float* r, int4 xi, float2 xf) {
    float a = r[xi.x], b = r[xi.y], c = r[xi.z], d = r[xi.w];
    return make_float2(fmaf(xf.x, b - a, a), fmaf(xf.y, d - c, c));
}

template<int H>
struct SC {
    int   rowoff;       // smem offset of source row y0
    float fy;
    ull   xlo2, xdf2;   // packed x-lerp at y0, packed (hi - lo)
};

template<int H>
__device__ __forceinline__ void sc_init(SC<H>& s, const float* sm, int y, int rlo,
                                        int4 xi, float2 xf) {
    int num = y * (H - 1);
    int y0 = num / 255;
    s.fy = (float)(num - 255 * y0) * (1.0f / 255.0f);
    s.rowoff = (y0 - rlo) * H;
    float2 lo = xl2(sm + s.rowoff, xi, xf);
    float2 hi = xl2(sm + s.rowoff + H, xi, xf);
    s.xlo2 = pk2(lo.x, lo.y);
    s.xdf2 = pk2(hi.x - lo.x, hi.y - lo.y);
}

template<int H>
__device__ __forceinline__ ull sc_m(const SC<H>& s) {
    return f2fma(pk2(s.fy, s.fy), s.xdf2, s.xlo2);
}

template<int H>
__device__ __forceinline__ void sc_adv(SC<H>& s, const float* sm,
                                       const int4* ti, const float2* tf, int tid) {
    s.fy += (float)(H - 1) * (1.0f / 255.0f);   // FADD immediate
    if (s.fy >= 1.0f) {                          // uniform, rarely taken
        s.fy -= 1.0f;
        s.rowoff += H;
        s.xlo2 = f2add(s.xlo2, s.xdf2);          // new lo = old hi
        float2 hi = xl2(sm + s.rowoff + H, ti[tid], tf[tid]);
        float2 lo = up2(s.xlo2);
        s.xdf2 = pk2(hi.x - lo.x, hi.y - lo.y);
    }
}

// packed 5-tap horizontal blur from smem row (row = &mbuf[r][2*tid])
__device__ __forceinline__ ull hblur(const float* row, ull w0p, ull w1p, ull w2p) {
    float2 a = *(const float2*)&row[0];   // m[-2], m[-1]
    float2 b = *(const float2*)&row[2];   // m[ 0], m[ 1]
    float2 c = *(const float2*)&row[4];   // m[ 2], m[ 3]
    ull p0 = pk2(a.x, a.y);
    ull p1 = pk2(a.y, b.x);
    ull p2 = pk2(b.x, b.y);
    ull p3 = pk2(b.y, c.x);
    ull p4 = pk2(c.x, c.y);
    return f2fma(w0p, f2add(p0, p4), f2fma(w1p, f2add(p1, p3), f2mul(w2p, p2)));
}

__global__ void __launch_bounds__(128, 8)
fused_quarter(const float* __restrict__ in0,
              const float* __restrict__ in1,
              const float* __restrict__ in2,
              float* __restrict__ maps,
              float* __restrict__ scores) {
    __shared__ __align__(16) float s0[20 * 64];
    __shared__ __align__(16) float s1[12 * 32];
    __shared__ __align__(16) float s2[8 * 16];
    __shared__ int4   ti0[128], ti1[128], ti2[128];
    __shared__ float2 tf0[128], tf1[128], tf2[128];
    __shared__ __align__(16) float mbuf[8][264];
    __shared__ float wred[4];

    const int tid = threadIdx.x;
    const int bx  = blockIdx.x;
    const int b   = bx >> 2;
    const int q   = bx & 3;
    const int yq0 = q * 64;

    const int amin = max(0, yq0 - 2);
    const int amax = min(255, yq0 + 65);
    const int rlo0 = (amin * 63) / 255;
    const int rlo1 = (amin * 31) / 255;
    const int rlo2 = (amin * 15) / 255;

    // stage sources (coalesced float4)
    {
        const int rhi = min((amax * 63) / 255 + 1, 63);
        const float4* g = (const float4*)(in0 + (size_t)b * 4096 + rlo0 * 64);
        int n = (rhi - rlo0 + 1) * 16;
        for (int i = tid; i < n; i += 128) ((float4*)s0)[i] = g[i];
    }
    {
        const int rhi = min((amax * 31) / 255 + 1, 31);
        const float4* g = (const float4*)(in1 + (size_t)b * 1024 + rlo1 * 32);
        int n = (rhi - rlo1 + 1) * 8;
        for (int i = tid; i < n; i += 128) ((float4*)s1)[i] = g[i];
    }
    {
        const int rhi = min((amax * 15) / 255 + 1, 15);
        const float4* g = (const float4*)(in2 + (size_t)b * 256 + rlo2 * 16);
        int n = (rhi - rlo2 + 1) * 4;
        for (int i = tid; i < n; i += 128) ((float4*)s2)[i] = g[i];
    }

    // build x tables (once per thread)
    {
        int c0 = 2 * tid, c1 = 2 * tid + 1;
        int n0 = c0 * 63, n1 = c1 * 63;
        int xa = n0 / 255, xb = n1 / 255;
        ti0[tid] = make_int4(xa, min(xa + 1, 63), xb, min(xb + 1, 63));
        tf0[tid] = make_float2((float)(n0 - 255 * xa) * (1.0f / 255.0f),
                               (float)(n1 - 255 * xb) * (1.0f / 255.0f));
        n0 = c0 * 31; n1 = c1 * 31;
        xa = n0 / 255; xb = n1 / 255;
        ti1[tid] = make_int4(xa, min(xa + 1, 31), xb, min(xb + 1, 31));
        tf1[tid] = make_float2((float)(n0 - 255 * xa) * (1.0f / 255.0f),
                               (float)(n1 - 255 * xb) * (1.0f / 255.0f));
        n0 = c0 * 15; n1 = c1 * 15;
        xa = n0 / 255; xb = n1 / 255;
        ti2[tid] = make_int4(xa, min(xa + 1, 15), xb, min(xb + 1, 15));
        tf2[tid] = make_float2((float)(n0 - 255 * xa) * (1.0f / 255.0f),
                               (float)(n1 - 255 * xb) * (1.0f / 255.0f));
    }

    const bool eL0 = (tid == 1), eL1 = (tid == 0);
    const bool eR0 = (tid == 127), eR1 = (tid == 126);
    const ull w0p = pk2(W0, W0), w1p = pk2(W1, W1), w2p = pk2(W2, W2);

    SC<64> cA; SC<32> cB; SC<16> cC;

    __syncthreads();

    const int4   xiA = ti0[tid]; const float2 xfA = tf0[tid];
    const int4   xiB = ti1[tid]; const float2 xfB = tf1[tid];
    const int4   xiC = ti2[tid]; const float2 xfC = tf2[tid];

    // ---- prime rows h(yq0-2), h(yq0-1) (reflect at top edge) ----
    {
        int p0 = (q == 0) ? 2 : yq0 - 2;
        int p1 = (q == 0) ? 1 : yq0 - 1;
        sc_init(cA, s0, p0, rlo0, xiA, xfA);
        sc_init(cB, s1, p0, rlo1, xiB, xfB);
        sc_init(cC, s2, p0, rlo2, xiC, xfC);
        ull m2 = f2add(f2add(sc_m(cA), sc_m(cB)), sc_m(cC));
        *(ull*)&mbuf[0][2 + 2 * tid] = m2;
        float2 mv = up2(m2);
        if (eL0) mbuf[0][0] = mv.x;
        if (eL1) mbuf[0][1] = mv.y;
        if (eR0) mbuf[0][258] = mv.x;
        if (eR1) mbuf[0][259] = mv.y;
        sc_init(cA, s0, p1, rlo0, xiA, xfA);
        sc_init(cB, s1, p1, rlo1, xiB, xfB);
        sc_init(cC, s2, p1, rlo2, xiC, xfC);
        m2 = f2add(f2add(sc_m(cA), sc_m(cB)), sc_m(cC));
        *(ull*)&mbuf[1][2 + 2 * tid] = m2;
        mv = up2(m2);
        if (eL0) mbuf[1][0] = mv.x;
        if (eL1) mbuf[1][1] = mv.y;
        if (eR0) mbuf[1][258] = mv.x;
        if (eR1) mbuf[1][259] = mv.y;
    }
    __syncthreads();
    ull ha = 0, hb = 0;
    ull hc = hblur(&mbuf[0][2 * tid], w0p, w1p, w2p);
    ull hd = hblur(&mbuf[1][2 * tid], w0p, w1p, w2p);
    __syncthreads();

    // ---- main strip: 8 phases x 8 rows ----
    sc_init(cA, s0, yq0, rlo0, xiA, xfA);
    sc_init(cB, s1, yq0, rlo1, xiB, xfB);
    sc_init(cC, s2, yq0, rlo2, xiC, xfC);

    float* mp = maps + (size_t)b * 65536 + (size_t)yq0 * 256 + 2 * tid;
    float lmax = -INFINITY;

    // peeled phase 0 (guards only here)
    {
        #pragma unroll
        for (int r = 0; r < 8; ++r) {
            ull m2 = f2add(f2add(sc_m(cA), sc_m(cB)), sc_m(cC));
            *(ull*)&mbuf[r][2 + 2 * tid] = m2;
            float2 mv = up2(m2);
            if (eL0) mbuf[r][0] = mv.x;
            if (eL1) mbuf[r][1] = mv.y;
            if (eR0) mbuf[r][258] = mv.x;
            if (eR1) mbuf[r][259] = mv.y;
            *(ull*)(mp + r * 256) = m2;
            sc_adv(cA, s0, ti0, tf0, tid);
            sc_adv(cB, s1, ti1, tf1, tid);
            sc_adv(cC, s2, ti2, tf2, tid);
        }
        mp += 2048;
        __syncthreads();
        #pragma unroll
        for (int r = 0; r < 8; ++r) {
            ull he = hblur(&mbuf[r][2 * tid], w0p, w1p, w2p);
            ull vv = f2fma(w0p, f2add(ha, he),
                     f2fma(w1p, f2add(hb, hd), f2mul(w2p, hc)));
            if (r >= 2) {
                float2 vf = up2(vv);
                lmax = fmaxf(lmax, fmaxf(vf.x, vf.y));
            }
            ha = hb; hb = hc; hc = hd; hd = he;
        }
        __syncthreads();
    }

    for (int p = 1; p < 8; ++p) {
        #pragma unroll
        for (int r = 0; r < 8; ++r) {
            ull m2 = f2add(f2add(sc_m(cA), sc_m(cB)), sc_m(cC));
            *(ull*)&mbuf[r][2 + 2 * tid] = m2;
            float2 mv = up2(m2);
            if (eL0) mbuf[r][0] = mv.x;
            if (eL1) mbuf[r][1] = mv.y;
            if (eR0) mbuf[r][258] = mv.x;
            if (eR1) mbuf[r][259] = mv.y;
            *(ull*)(mp + r * 256) = m2;
            sc_adv(cA, s0, ti0, tf0, tid);
            sc_adv(cB, s1, ti1, tf1, tid);
            sc_adv(cC, s2, ti2, tf2, tid);
        }
        mp += 2048;
        __syncthreads();
        #pragma unroll
        for (int r = 0; r < 8; ++r) {
            ull he = hblur(&mbuf[r][2 * tid], w0p, w1p, w2p);
            ull vv = f2fma(w0p, f2add(ha, he),
                     f2fma(w1p, f2add(hb, hd), f2mul(w2p, hc)));
            float2 vf = up2(vv);
            lmax = fmaxf(lmax, fmaxf(vf.x, vf.y));
            ha = hb; hb = hc; hc = hd; hd = he;
        }
        __syncthreads();
    }

    if (q < 3) {
        // rows yq0+64, yq0+65 finish v rows yq0+62, yq0+63
        #pragma unroll
        for (int e = 0; e < 2; ++e) {
            ull m2 = f2add(f2add(sc_m(cA), sc_m(cB)), sc_m(cC));
            *(ull*)&mbuf[e][2 + 2 * tid] = m2;
            float2 mv = up2(m2);
            if (eL0) mbuf[e][0] = mv.x;
            if (eL1) mbuf[e][1] = mv.y;
            if (eR0) mbuf[e][258] = mv.x;
            if (eR1) mbuf[e][259] = mv.y;
            sc_adv(cA, s0, ti0, tf0, tid);
            sc_adv(cB, s1, ti1, tf1, tid);
            sc_adv(cC, s2, ti2, tf2, tid);
        }
        __syncthreads();
        #pragma unroll
        for (int e = 0; e < 2; ++e) {
            ull he = hblur(&mbuf[e][2 * tid], w0p, w1p, w2p);
            ull vv = f2fma(w0p, f2add(ha, he),
                     f2fma(w1p, f2add(hb, hd), f2mul(w2p, hc)));
            float2 vf = up2(vv);
            lmax = fmaxf(lmax, fmaxf(vf.x, vf.y));
            ha = hb; hb = hc; hc = hd; hd = he;
        }
    } else {
        // ring holds h252..h255; reflect rows 256->254, 257->253
        ull v254 = f2fma(w0p, f2add(ha, hc), f2fma(w1p, f2add(hb, hd), f2mul(w2p, hc)));
        ull v255 = f2fma(w0p, f2add(hb, hb), f2fma(w1p, f2add(hc, hc), f2mul(w2p, hd)));
        float2 a4 = up2(v254), a5 = up2(v255);
        lmax = fmaxf(lmax, fmaxf(fmaxf(a4.x, a4.y), fmaxf(a5.x, a5.y)));
    }

    // block max -> fused per-batch reduction (max is order-independent;
    // last-arriving block decodes and resets scratch for graph replay)
    #pragma unroll
    for (int off = 16; off; off >>= 1)
        lmax = fmaxf(lmax, __shfl_xor_sync(0xFFFFFFFFu, lmax, off));
    if ((tid & 31) == 0) wred[tid >> 5] = lmax;
    __syncthreads();
    if (tid == 0) {
        float m = fmaxf(fmaxf(wred[0], wred[1]), fmaxf(wred[2], wred[3]));
        atomicMax(&g_enc[b], enc_f(m));
        __threadfence();
        unsigned t = atomicAdd(&g_cnt[b], 1u);
        if (t == 3u) {
            unsigned e = atomicExch(&g_enc[b], 0u);
            scores[b] = dec_f(e);
            atomicExch(&g_cnt[b], 0u);
        }
    }
}

extern "C" void kernel_launch(void* const* d_in, const int* in_sizes, int n_in,
                              void* d_out, int out_size) {
    const float* out0 = (const float*)d_in[0];  // [256,64,64]
    const float* out1 = (const float*)d_in[1];  // [256,32,32]
    const float* out2 = (const float*)d_in[2];  // [256,16,16]
    float* out = (float*)d_out;

    fused_quarter<<<1024, 128>>>(out0, out1, out2, out + 256, out);
}

// round 7
// speedup vs baseline: 1.6648x; 1.1570x over previous
#include <cuda_runtime.h>
#include <math.h>

// ---------------------------------------------------------------------------
// maps[b] = bilin_up(out0,64)+bilin_up(out1,32)+bilin_up(out2,16) -> 256x256
// scores[b] = max( reflect-pad 5x5 gaussian blur of maps[b] )
// d_out = [256 scores][256*256*256 maps] fp32.
//
// 1024 blocks = (batch, 64-row quarter strip), 128 threads = column pairs.
// Incremental bilinear with packed-f32x2 fy tracking (wrap on fy>=1; x-lerp
// brackets recomputed only inside the rare uniform wrap branch), guard row per
// staged scale so the hi-row read at y0=H-1 is always defined, single-slot
// halo store, 8-row smem ring for the h-blur halo, register ring v-blur.
// Fused per-batch max via encoded atomicMax + arrival counter.
// ---------------------------------------------------------------------------

typedef unsigned long long ull;

#define W0 0.18762723f
#define W1 0.20606817f
#define W2 0.21260941f

__device__ __forceinline__ ull pk2(float a, float b) {
    ull r; asm("mov.b64 %0, {%1,%2};" : "=l"(r) : "f"(a), "f"(b)); return r;
}
__device__ __forceinline__ float2 up2(ull v) {
    float2 r; asm("mov.b64 {%0,%1}, %2;" : "=f"(r.x), "=f"(r.y) : "l"(v)); return r;
}
__device__ __forceinline__ ull f2add(ull a, ull b) {
    ull r; asm("add.rn.f32x2 %0,%1,%2;" : "=l"(r) : "l"(a), "l"(b)); return r;
}
__device__ __forceinline__ ull f2mul(ull a, ull b) {
    ull r; asm("mul.rn.f32x2 %0,%1,%2;" : "=l"(r) : "l"(a), "l"(b)); return r;
}
__device__ __forceinline__ ull f2fma(ull a, ull b, ull c) {
    ull r; asm("fma.rn.f32x2 %0,%1,%2,%3;" : "=l"(r) : "l"(a), "l"(b), "l"(c)); return r;
}

__device__ __forceinline__ unsigned enc_f(float f) {
    unsigned u = __float_as_uint(f);
    return (u & 0x80000000u) ? ~u : (u | 0x80000000u);
}
__device__ __forceinline__ float dec_f(unsigned u) {
    return (u & 0x80000000u) ? __uint_as_float(u & 0x7fffffffu)
                             : __uint_as_float(~u);
}

__device__ unsigned g_enc[256];   // zero-init; reset by last block each call
__device__ unsigned g_cnt[256];   // zero-init; reset by last block each call

template<int H>
struct SC {
    int rowoff;          // smem offset of source row y0
    ull fy2;             // packed (fy, fy)
    ull xlo2, xdf2;      // packed x-lerp at y0, packed (hi - lo)
};

// x-lerp of this thread's column pair from a staged source row
template<int H>
__device__ __forceinline__ float2 xlerp(const float* row, int tid) {
    int n0 = 2 * tid * (H - 1), n1 = n0 + (H - 1);
    int xa = n0 / 255, xb = n1 / 255;
    float fxa = (float)(n0 - 255 * xa) * (1.0f / 255.0f);
    float fxb = (float)(n1 - 255 * xb) * (1.0f / 255.0f);
    int xa1 = min(xa + 1, H - 1), xb1 = min(xb + 1, H - 1);
    float A = row[xa], B = row[xa1], C = row[xb], D = row[xb1];
    return make_float2(fmaf(fxa, B - A, A), fmaf(fxb, D - C, C));
}

template<int H>
__device__ __forceinline__ void sc_init(SC<H>& s, const float* sm, int y, int rlo, int tid) {
    int num = y * (H - 1);
    int y0 = num / 255;
    float fy = (float)(num - 255 * y0) * (1.0f / 255.0f);
    s.fy2 = pk2(fy, fy);
    s.rowoff = (y0 - rlo) * H;
    float2 lo = xlerp<H>(sm + s.rowoff, tid);
    float2 hi = xlerp<H>(sm + s.rowoff + H, tid);   // guard row keeps this defined
    s.xlo2 = pk2(lo.x, lo.y);
    s.xdf2 = pk2(hi.x - lo.x, hi.y - lo.y);
}

template<int H>
__device__ __forceinline__ ull sc_m(const SC<H>& s) {
    return f2fma(s.fy2, s.xdf2, s.xlo2);
}

template<int H>
__device__ __forceinline__ void sc_adv(SC<H>& s, const float* sm, ull inc2, ull m1_2, int tid) {
    s.fy2 = f2add(s.fy2, inc2);
    if (up2(s.fy2).x >= 1.0f) {       // uniform, rarely taken
        s.fy2 = f2add(s.fy2, m1_2);
        s.rowoff += H;
        s.xlo2 = f2add(s.xlo2, s.xdf2);            // new lo = old hi
        float2 hi = xlerp<H>(sm + s.rowoff + H, tid);
        float2 lo = up2(s.xlo2);
        s.xdf2 = pk2(hi.x - lo.x, hi.y - lo.y);
    }
}

// packed 5-tap horizontal blur from smem row (row = &mbuf[r][2*tid])
__device__ __forceinline__ ull hblur(const float* row, ull w0p, ull w1p, ull w2p) {
    float2 a = *(const float2*)&row[0];   // m[-2], m[-1]
    float2 b = *(const float2*)&row[2];   // m[ 0], m[ 1]
    float2 c = *(const float2*)&row[4];   // m[ 2], m[ 3]
    ull p0 = pk2(a.x, a.y);
    ull p1 = pk2(a.y, b.x);
    ull p2 = pk2(b.x, b.y);
    ull p3 = pk2(b.y, c.x);
    ull p4 = pk2(c.x, c.y);
    return f2fma(w0p, f2add(p0, p4), f2fma(w1p, f2add(p1, p3), f2mul(w2p, p2)));
}

__global__ void __launch_bounds__(128, 8)
fused_quarter(const float* __restrict__ in0,
              const float* __restrict__ in1,
              const float* __restrict__ in2,
              float* __restrict__ maps,
              float* __restrict__ scores) {
    __shared__ __align__(16) float s0[20 * 64];   // staged + guard row
    __shared__ __align__(16) float s1[12 * 32];
    __shared__ __align__(16) float s2[8 * 16];
    __shared__ __align__(16) float mbuf[8][264];  // [0..259] used, [260..263] dummy
    __shared__ float wred[4];

    const int tid = threadIdx.x;
    const int bx  = blockIdx.x;
    const int b   = bx >> 2;
    const int q   = bx & 3;
    const int yq0 = q * 64;

    const int amin = max(0, yq0 - 2);
    const int amax = min(255, yq0 + 65);
    const int rlo0 = (amin * 63) / 255;
    const int rlo1 = (amin * 31) / 255;
    const int rlo2 = (amin * 15) / 255;
    const int rhi0 = min((amax * 63) / 255 + 1, 63);
    const int rhi1 = min((amax * 31) / 255 + 1, 31);
    const int rhi2 = min((amax * 15) / 255 + 1, 15);

    // stage sources (coalesced float4) + guard row (duplicate of last row)
    {
        const float* gb = in0 + (size_t)b * 4096 + rlo0 * 64;
        int n = (rhi0 - rlo0 + 1) * 16;
        for (int i = tid; i < n; i += 128) ((float4*)s0)[i] = ((const float4*)gb)[i];
        const float* gr = in0 + (size_t)b * 4096 + rhi0 * 64;
        if (tid < 64) s0[n * 4 + tid] = gr[tid];
    }
    {
        const float* gb = in1 + (size_t)b * 1024 + rlo1 * 32;
        int n = (rhi1 - rlo1 + 1) * 8;
        for (int i = tid; i < n; i += 128) ((float4*)s1)[i] = ((const float4*)gb)[i];
        const float* gr = in1 + (size_t)b * 1024 + rhi1 * 32;
        if (tid < 32) s1[n * 4 + tid] = gr[tid];
    }
    {
        const float* gb = in2 + (size_t)b * 256 + rlo2 * 16;
        int n = (rhi2 - rlo2 + 1) * 4;
        for (int i = tid; i < n; i += 128) ((float4*)s2)[i] = ((const float4*)gb)[i];
        const float* gr = in2 + (size_t)b * 256 + rhi2 * 16;
        if (tid < 16) s2[n * 4 + tid] = gr[tid];
    }

    // per-thread halo-store slot: threads 0/1/126/127 fill reflect cells,
    // everyone else hits the dummy pad (same-address stores collapse).
    int hoff; bool pickY;
    if (tid == 1)        { hoff = 0;   pickY = false; }
    else if (tid == 0)   { hoff = 1;   pickY = true;  }
    else if (tid == 127) { hoff = 258; pickY = false; }
    else if (tid == 126) { hoff = 259; pickY = true;  }
    else                 { hoff = 260; pickY = false; }

    const ull w0p = pk2(W0, W0), w1p = pk2(W1, W1), w2p = pk2(W2, W2);
    const ull incA = pk2(63.0f / 255.0f, 63.0f / 255.0f);
    const ull incB = pk2(31.0f / 255.0f, 31.0f / 255.0f);
    const ull incC = pk2(15.0f / 255.0f, 15.0f / 255.0f);
    const ull m1_2 = pk2(-1.0f, -1.0f);

    SC<64> cA; SC<32> cB; SC<16> cC;

    __syncthreads();

    // ---- prime rows h(yq0-2), h(yq0-1) (reflect at top edge) ----
    {
        int p0 = (q == 0) ? 2 : yq0 - 2;
        int p1 = (q == 0) ? 1 : yq0 - 1;
        sc_init(cA, s0, p0, rlo0, tid);
        sc_init(cB, s1, p0, rlo1, tid);
        sc_init(cC, s2, p0, rlo2, tid);
        ull m2 = f2add(f2add(sc_m(cA), sc_m(cB)), sc_m(cC));
        *(ull*)&mbuf[0][2 + 2 * tid] = m2;
        float2 mv = up2(m2);
        mbuf[0][hoff] = pickY ? mv.y : mv.x;
        sc_init(cA, s0, p1, rlo0, tid);
        sc_init(cB, s1, p1, rlo1, tid);
        sc_init(cC, s2, p1, rlo2, tid);
        m2 = f2add(f2add(sc_m(cA), sc_m(cB)), sc_m(cC));
        *(ull*)&mbuf[1][2 + 2 * tid] = m2;
        mv = up2(m2);
        mbuf[1][hoff] = pickY ? mv.y : mv.x;
    }
    __syncthreads();
    ull ha = 0, hb = 0;
    ull hc = hblur(&mbuf[0][2 * tid], w0p, w1p, w2p);
    ull hd = hblur(&mbuf[1][2 * tid], w0p, w1p, w2p);
    __syncthreads();

    // ---- main strip: 8 phases x 8 rows ----
    sc_init(cA, s0, yq0, rlo0, tid);
    sc_init(cB, s1, yq0, rlo1, tid);
    sc_init(cC, s2, yq0, rlo2, tid);

    float* mp = maps + (size_t)b * 65536 + (size_t)yq0 * 256 + 2 * tid;
    float lmax = -INFINITY;

    // peeled phase 0 (max-guard only here)
    {
        #pragma unroll
        for (int r = 0; r < 8; ++r) {
            ull m2 = f2add(f2add(sc_m(cA), sc_m(cB)), sc_m(cC));
            *(ull*)&mbuf[r][2 + 2 * tid] = m2;
            float2 mv = up2(m2);
            mbuf[r][hoff] = pickY ? mv.y : mv.x;
            *(ull*)(mp + r * 256) = m2;
            sc_adv(cA, s0, incA, m1_2, tid);
            sc_adv(cB, s1, incB, m1_2, tid);
            sc_adv(cC, s2, incC, m1_2, tid);
        }
        mp += 2048;
        __syncthreads();
        #pragma unroll
        for (int r = 0; r < 8; ++r) {
            ull he = hblur(&mbuf[r][2 * tid], w0p, w1p, w2p);
            ull vv = f2fma(w0p, f2add(ha, he),
                     f2fma(w1p, f2add(hb, hd), f2mul(w2p, hc)));
            if (r >= 2) {
                float2 vf = up2(vv);
                lmax = fmaxf(lmax, fmaxf(vf.x, vf.y));
            }
            ha = hb; hb = hc; hc = hd; hd = he;
        }
        __syncthreads();
    }

    for (int p = 1; p < 8; ++p) {
        #pragma unroll
        for (int r = 0; r < 8; ++r) {
            ull m2 = f2add(f2add(sc_m(cA), sc_m(cB)), sc_m(cC));
            *(ull*)&mbuf[r][2 + 2 * tid] = m2;
            float2 mv = up2(m2);
            mbuf[r][hoff] = pickY ? mv.y : mv.x;
            *(ull*)(mp + r * 256) = m2;
            sc_adv(cA, s0, incA, m1_2, tid);
            sc_adv(cB, s1, incB, m1_2, tid);
            sc_adv(cC, s2, incC, m1_2, tid);
        }
        mp += 2048;
        __syncthreads();
        #pragma unroll
        for (int r = 0; r < 8; ++r) {
            ull he = hblur(&mbuf[r][2 * tid], w0p, w1p, w2p);
            ull vv = f2fma(w0p, f2add(ha, he),
                     f2fma(w1p, f2add(hb, hd), f2mul(w2p, hc)));
            float2 vf = up2(vv);
            lmax = fmaxf(lmax, fmaxf(vf.x, vf.y));
            ha = hb; hb = hc; hc = hd; hd = he;
        }
        __syncthreads();
    }

    if (q < 3) {
        // rows yq0+64, yq0+65 finish v rows yq0+62, yq0+63
        #pragma unroll
        for (int e = 0; e < 2; ++e) {
            ull m2 = f2add(f2add(sc_m(cA), sc_m(cB)), sc_m(cC));
            *(ull*)&mbuf[e][2 + 2 * tid] = m2;
            float2 mv = up2(m2);
            mbuf[e][hoff] = pickY ? mv.y : mv.x;
            sc_adv(cA, s0, incA, m1_2, tid);
            sc_adv(cB, s1, incB, m1_2, tid);
            sc_adv(cC, s2, incC, m1_2, tid);
        }
        __syncthreads();
        #pragma unroll
        for (int e = 0; e < 2; ++e) {
            ull he = hblur(&mbuf[e][2 * tid], w0p, w1p, w2p);
            ull vv = f2fma(w0p, f2add(ha, he),
                     f2fma(w1p, f2add(hb, hd), f2mul(w2p, hc)));
            float2 vf = up2(vv);
            lmax = fmaxf(lmax, fmaxf(vf.x, vf.y));
            ha = hb; hb = hc; hc = hd; hd = he;
        }
    } else {
        // ring holds h252..h255; reflect rows 256->254, 257->253
        ull v254 = f2fma(w0p, f2add(ha, hc), f2fma(w1p, f2add(hb, hd), f2mul(w2p, hc)));
        ull v255 = f2fma(w0p, f2add(hb, hb), f2fma(w1p, f2add(hc, hc), f2mul(w2p, hd)));
        float2 a4 = up2(v254), a5 = up2(v255);
        lmax = fmaxf(lmax, fmaxf(fmaxf(a4.x, a4.y), fmaxf(a5.x, a5.y)));
    }

    // block max -> fused per-batch reduction (max is order-independent;
    // last-arriving block decodes and resets scratch for graph replay)
    #pragma unroll
    for (int off = 16; off; off >>= 1)
        lmax = fmaxf(lmax, __shfl_xor_sync(0xFFFFFFFFu, lmax, off));
    if ((tid & 31) == 0) wred[tid >> 5] = lmax;
    __syncthreads();
    if (tid == 0) {
        float m = fmaxf(fmaxf(wred[0], wred[1]), fmaxf(wred[2], wred[3]));
        atomicMax(&g_enc[b], enc_f(m));
        __threadfence();
        unsigned t = atomicAdd(&g_cnt[b], 1u);
        if (t == 3u) {
            unsigned e = atomicExch(&g_enc[b], 0u);
            scores[b] = dec_f(e);
            atomicExch(&g_cnt[b], 0u);
        }
    }
}

extern "C" void kernel_launch(void* const* d_in, const int* in_sizes, int n_in,
                              void* d_out, int out_size) {
    const float* out0 = (const float*)d_in[0];  // [256,64,64]
    const float* out1 = (const float*)d_in[1];  // [256,32,32]
    const float* out2 = (const float*)d_in[2];  // [256,16,16]
    float* out = (float*)d_out;

    fused_quarter<<<1024, 128>>>(out0, out1, out2, out + 256, out);
}